// round 1
// baseline (speedup 1.0000x reference)
#include <cuda_runtime.h>
#include <math.h>

#define NV 50000
#define ME 800000
#define EE 64
#define FE 41
#define FV 92
#define NL 3
#define CC 169      // 2*EE + FE
#define FC0 128
#define FC1 64
#define NG 256
#define EPSB 1e-5f

// ---------------- scratch (device globals; no allocation allowed) ----------------
__device__ float g_tmp[NV * EE];                  // pre-BN embedding
__device__ float g_v[NV * EE];                    // node state
__device__ float g_A[4L * NV * EE];               // Am | Bm | As | Bs node projections
__device__ float g_C[(size_t)ME * 2 * EE];        // per-edge edge-feature projections (gate|screen)
__device__ float g_agg[NV * EE];                  // scatter target
__device__ float g_stats[256];                    // edge stats: sum_m[64] sum_s[64] sq_m[64] sq_s[64]
__device__ float g_stats2[128];                   // node/embed stats: sum[64] sq[64]
__device__ float g_bnpE[256];                     // mean_m mean_s rstd_m rstd_s
__device__ float g_bnpN[128];                     // mean rstd
__device__ float g_pool[NG * EE];
__device__ float g_cnt[NG];
__device__ float g_r0[NG * EE];
__device__ float g_r1[NG * FC0];
__device__ float g_r2[NG * FC1];

__device__ __forceinline__ float sigmoidf_(float x) { return 1.f / (1.f + __expf(-x)); }
__device__ __forceinline__ float softplusf_(float x) {
    return fmaxf(x, 0.f) + log1pf(__expf(-fabsf(x)));
}

// ---------------- init: zero pool/cnt + embed stats ----------------
__global__ void k_init() {
    int i = blockIdx.x * blockDim.x + threadIdx.x;
    int stride = gridDim.x * blockDim.x;
    for (int j = i; j < NG * EE; j += stride) g_pool[j] = 0.f;
    for (int j = i; j < NG; j += stride) g_cnt[j] = 0.f;
    for (int j = i; j < 128; j += stride) g_stats2[j] = 0.f;
}

// ---------------- embedding GEMM + stats ----------------
__global__ void k_embed(const float* __restrict__ nf, const float* __restrict__ W,
                        const float* __restrict__ b) {
    __shared__ float sW[FV * EE];          // 23.5 KB
    __shared__ float snf[4 * FV];
    __shared__ float sred[256];
    int tid = threadIdx.x;
    int c = tid & 63, ry = tid >> 6;
    for (int i = tid; i < FV * EE; i += 256) sW[i] = W[i];
    float bias = b[c];
    float s1 = 0.f, s2 = 0.f;
    __syncthreads();
    for (int row0 = blockIdx.x * 4; row0 < NV; row0 += gridDim.x * 4) {
        for (int i = tid; i < 4 * FV; i += 256) snf[i] = nf[(size_t)row0 * FV + i];
        __syncthreads();
        float acc = bias;
#pragma unroll
        for (int k = 0; k < FV; k++) acc = fmaf(snf[ry * FV + k], sW[k * EE + c], acc);
        g_tmp[(row0 + ry) * EE + c] = acc;
        s1 += acc; s2 += acc * acc;
        __syncthreads();
    }
    sred[tid] = s1; __syncthreads();
    if (tid < 64) atomicAdd(&g_stats2[tid], sred[tid] + sred[tid + 64] + sred[tid + 128] + sred[tid + 192]);
    __syncthreads();
    sred[tid] = s2; __syncthreads();
    if (tid < 64) atomicAdd(&g_stats2[64 + tid], sred[tid] + sred[tid + 64] + sred[tid + 128] + sred[tid + 192]);
}

// ---------------- finalize batch stats -> mean, rstd ----------------
__global__ void k_finalize(const float* __restrict__ s, float* __restrict__ o,
                           int ncols, float invc) {
    int i = blockIdx.x * blockDim.x + threadIdx.x;
    if (i < ncols) {
        float m = s[i] * invc;
        float var = s[ncols + i] * invc - m * m;
        o[i] = m;
        o[ncols + i] = rsqrtf(var + EPSB);
    }
}

// ---------------- embed BN + SiLU ----------------
__global__ void k_embed_apply(const float* __restrict__ g, const float* __restrict__ be) {
    int i = blockIdx.x * blockDim.x + threadIdx.x;
    if (i >= NV * EE) return;
    int c = i & 63;
    float x = g_tmp[i];
    float xn = (x - g_bnpN[c]) * g_bnpN[64 + c] * g[c] + be[c];
    g_v[i] = xn * sigmoidf_(xn);
}

// ---------------- node projections: A = v @ {Wm_src,Wm_dst,Ws_src,Ws_dst} ----------------
__global__ void k_nodeproj(const float* __restrict__ Wm, const float* __restrict__ Ws, int l) {
    if (blockIdx.x == 0 && threadIdx.x < 256) g_stats[threadIdx.x] = 0.f;  // zero edge stats
    int tid = threadIdx.x;
    int t = tid >> 6, col = tid & 63;
    const float* base = ((t < 2) ? Wm : Ws) + (size_t)l * CC * EE + (size_t)(t & 1) * (64 * EE) + col;
    float w[64];
#pragma unroll
    for (int k = 0; k < 64; k++) w[k] = base[(size_t)k * EE];
    __shared__ __align__(16) float sv[256];
    float* outb = g_A + (size_t)t * NV * EE + col;
    for (int row0 = blockIdx.x * 4; row0 < NV; row0 += gridDim.x * 4) {
        __syncthreads();
        sv[tid] = g_v[row0 * EE + tid];
        __syncthreads();
#pragma unroll
        for (int r = 0; r < 4; r++) {
            float acc = 0.f;
#pragma unroll
            for (int k4 = 0; k4 < 16; k4++) {
                float4 vv = *reinterpret_cast<const float4*>(&sv[r * 64 + k4 * 4]);
                acc = fmaf(vv.x, w[k4 * 4 + 0], acc);
                acc = fmaf(vv.y, w[k4 * 4 + 1], acc);
                acc = fmaf(vv.z, w[k4 * 4 + 2], acc);
                acc = fmaf(vv.w, w[k4 * 4 + 3], acc);
            }
            outb[(size_t)(row0 + r) * EE] = acc;
        }
    }
}

// ---------------- edge-feature projection C = ef @ [Wm_e|Ws_e] + [bm|bs] ----------------
__global__ void k_cgemm(const float* __restrict__ ef, const float* __restrict__ Wm,
                        const float* __restrict__ Ws, const float* __restrict__ bm,
                        const float* __restrict__ bs, int l) {
    int tid = threadIdx.x;               // 128 threads
    int col = tid & 63, t = tid >> 6;    // t=0 gate (Wm), t=1 screen (Ws)
    const float* base = (t == 0 ? Wm : Ws) + (size_t)l * CC * EE + (size_t)128 * EE + col;
    float w[44];
#pragma unroll
    for (int k = 0; k < FE; k++) w[k] = base[(size_t)k * EE];
#pragma unroll
    for (int k = FE; k < 44; k++) w[k] = 0.f;
    float bias = (t == 0 ? bm : bs)[l * EE + col];
    __shared__ __align__(16) float sef[4 * 44];
    for (int e0 = blockIdx.x * 4; e0 < ME; e0 += gridDim.x * 4) {
        __syncthreads();
        for (int i = tid; i < 4 * FE; i += 128) {
            int r = i / FE, k = i - r * FE;
            sef[r * 44 + k] = ef[(size_t)e0 * FE + i];
        }
        if (tid < 12) { int r = tid / 3, k = FE + tid % 3; sef[r * 44 + k] = 0.f; }
        __syncthreads();
#pragma unroll
        for (int r = 0; r < 4; r++) {
            float acc = bias;
#pragma unroll
            for (int k4 = 0; k4 < 11; k4++) {
                float4 vv = *reinterpret_cast<const float4*>(&sef[r * 44 + k4 * 4]);
                acc = fmaf(vv.x, w[k4 * 4 + 0], acc);
                acc = fmaf(vv.y, w[k4 * 4 + 1], acc);
                acc = fmaf(vv.z, w[k4 * 4 + 2], acc);
                acc = fmaf(vv.w, w[k4 * 4 + 3], acc);
            }
            g_C[((size_t)(e0 + r)) * 128 + tid] = acc;
        }
    }
}

// ---------------- edge pass 1: BN stats over M (also zeroes agg) ----------------
__global__ void k_edgestats(const int* __restrict__ src, const int* __restrict__ dst) {
    int tid = threadIdx.x;
    int gsz = gridDim.x * blockDim.x;
    for (int i = blockIdx.x * blockDim.x + tid; i < NV * EE; i += gsz) g_agg[i] = 0.f;
    int c = tid & 63, sub = tid >> 6;
    const float* Am = g_A;
    const float* Bm = g_A + (size_t)NV * EE;
    const float* As = g_A + (size_t)2 * NV * EE;
    const float* Bs = g_A + (size_t)3 * NV * EE;
    float sm = 0.f, qm = 0.f, ss = 0.f, qs = 0.f;
    for (int e = blockIdx.x * 4 + sub; e < ME; e += gridDim.x * 4) {
        int s = __ldg(src + e), d = __ldg(dst + e);
        float hm = Am[s * EE + c] + Bm[d * EE + c] + g_C[(size_t)e * 128 + c];
        float hs = As[s * EE + c] + Bs[d * EE + c] + g_C[(size_t)e * 128 + 64 + c];
        sm += hm; qm += hm * hm; ss += hs; qs += hs * hs;
    }
    __shared__ float sred[256];
    sred[tid] = sm; __syncthreads();
    if (tid < 64) atomicAdd(&g_stats[tid], sred[tid] + sred[tid + 64] + sred[tid + 128] + sred[tid + 192]);
    __syncthreads();
    sred[tid] = ss; __syncthreads();
    if (tid < 64) atomicAdd(&g_stats[64 + tid], sred[tid] + sred[tid + 64] + sred[tid + 128] + sred[tid + 192]);
    __syncthreads();
    sred[tid] = qm; __syncthreads();
    if (tid < 64) atomicAdd(&g_stats[128 + tid], sred[tid] + sred[tid + 64] + sred[tid + 128] + sred[tid + 192]);
    __syncthreads();
    sred[tid] = qs; __syncthreads();
    if (tid < 64) atomicAdd(&g_stats[192 + tid], sred[tid] + sred[tid + 64] + sred[tid + 128] + sred[tid + 192]);
}

// ---------------- edge pass 2: BN + sigmoid*softplus, scatter to agg[dst] ----------------
__global__ void k_edgeapply(const int* __restrict__ src, const int* __restrict__ dst,
                            const float* __restrict__ gm, const float* __restrict__ bem,
                            const float* __restrict__ gs, const float* __restrict__ bes, int l) {
    int tid = threadIdx.x;
    if (blockIdx.x == 0 && tid < 128) g_stats2[tid] = 0.f;  // zero node stats
    int c = tid & 63, sub = tid >> 6;
    float mm = g_bnpE[c], ms = g_bnpE[64 + c];
    float rm = g_bnpE[128 + c], rs = g_bnpE[192 + c];
    float gmc = gm[l * EE + c] * rm, bemc = bem[l * EE + c] - mm * gmc;
    float gsc = gs[l * EE + c] * rs, besc = bes[l * EE + c] - ms * gsc;
    const float* Am = g_A;
    const float* Bm = g_A + (size_t)NV * EE;
    const float* As = g_A + (size_t)2 * NV * EE;
    const float* Bs = g_A + (size_t)3 * NV * EE;
    for (int e = blockIdx.x * 4 + sub; e < ME; e += gridDim.x * 4) {
        int s = __ldg(src + e), d = __ldg(dst + e);
        float hm = Am[s * EE + c] + Bm[d * EE + c] + g_C[(size_t)e * 128 + c];
        float hs = As[s * EE + c] + Bs[d * EE + c] + g_C[(size_t)e * 128 + 64 + c];
        float gate = sigmoidf_(fmaf(hm, gmc, bemc));
        float scr = softplusf_(fmaf(hs, gsc, besc));
        atomicAdd(&g_agg[d * EE + c], gate * scr);
    }
}

// ---------------- node BN stats over N ----------------
__global__ void k_nodestats() {
    int tid = threadIdx.x;
    int c = tid & 63, sub = tid >> 6;
    float s1 = 0.f, s2 = 0.f;
    for (int n = blockIdx.x * 4 + sub; n < NV; n += gridDim.x * 4) {
        float x = g_agg[n * EE + c];
        s1 += x; s2 += x * x;
    }
    __shared__ float sred[256];
    sred[tid] = s1; __syncthreads();
    if (tid < 64) atomicAdd(&g_stats2[tid], sred[tid] + sred[tid + 64] + sred[tid + 128] + sred[tid + 192]);
    __syncthreads();
    sred[tid] = s2; __syncthreads();
    if (tid < 64) atomicAdd(&g_stats2[64 + tid], sred[tid] + sred[tid + 64] + sred[tid + 128] + sred[tid + 192]);
}

// ---------------- node update: v = softplus(BN(agg) + v) ----------------
__global__ void k_nodeapply(const float* __restrict__ gn, const float* __restrict__ ben, int l) {
    int i = blockIdx.x * blockDim.x + threadIdx.x;
    if (i >= NV * EE) return;
    int c = i & 63;
    float a = g_agg[i];
    float an = (a - g_bnpN[c]) * g_bnpN[64 + c] * gn[l * EE + c] + ben[l * EE + c];
    g_v[i] = softplusf_(an + g_v[i]);
}

// ---------------- graph pooling (graph_ids sorted -> run-length accumulate) ----------------
__global__ void k_pool(const int* __restrict__ gid) {
    __shared__ int sg[256];
    int tid = threadIdx.x;   // 64
    int n0 = blockIdx.x * 256;
    int nmax = min(256, NV - n0);
    for (int i = tid; i < nmax; i += 64) sg[i] = gid[n0 + i];
    __syncthreads();
    int cur = sg[0];
    float acc = 0.f, ccnt = 0.f;
    for (int i = 0; i < nmax; i++) {
        int g = sg[i];
        if (g != cur) {
            atomicAdd(&g_pool[cur * EE + tid], acc);
            if (tid == 0) atomicAdd(&g_cnt[cur], ccnt);
            acc = 0.f; ccnt = 0.f; cur = g;
        }
        acc += g_v[(n0 + i) * EE + tid];
        ccnt += 1.f;
    }
    atomicAdd(&g_pool[cur * EE + tid], acc);
    if (tid == 0) atomicAdd(&g_cnt[cur], ccnt);
}

__global__ void k_meanpool() {
    int i = blockIdx.x * blockDim.x + threadIdx.x;
    if (i < NG * EE) g_r0[i] = g_pool[i] / fmaxf(g_cnt[i >> 6], 1.f);
}

// ---------------- fused FC + BN(batch=256) + SiLU ----------------
template <int CI, int CO>
__global__ void k_fc(const float* __restrict__ in, const float* __restrict__ W,
                     const float* __restrict__ b, const float* __restrict__ gam,
                     const float* __restrict__ bet, float* __restrict__ out) {
    int r = threadIdx.x;   // 256 rows
    int co = blockIdx.x;
    float acc = b[co];
    for (int k = 0; k < CI; k++) acc = fmaf(in[r * CI + k], __ldg(&W[k * CO + co]), acc);
    __shared__ float sred[256];
    sred[r] = acc; __syncthreads();
    for (int s = 128; s > 0; s >>= 1) { if (r < s) sred[r] += sred[r + s]; __syncthreads(); }
    float m = sred[0] / 256.f;
    __syncthreads();
    sred[r] = acc * acc; __syncthreads();
    for (int s = 128; s > 0; s >>= 1) { if (r < s) sred[r] += sred[r + s]; __syncthreads(); }
    float var = sred[0] / 256.f - m * m;
    float rstd = rsqrtf(var + EPSB);
    float y = (acc - m) * rstd * gam[co] + bet[co];
    out[r * CO + co] = y * sigmoidf_(y);
}

__global__ void k_head(const float* __restrict__ Wt, const float* __restrict__ bt,
                       float* __restrict__ out) {
    int r = threadIdx.x;
    float acc = bt[0];
#pragma unroll
    for (int k = 0; k < FC1; k++) acc = fmaf(g_r2[r * FC1 + k], __ldg(&Wt[k]), acc);
    out[r] = acc;
}

// ---------------- launch ----------------
extern "C" void kernel_launch(void* const* d_in, const int* in_sizes, int n_in,
                              void* d_out, int out_size) {
    const float* nf    = (const float*)d_in[0];
    const float* ef    = (const float*)d_in[1];
    const int*   src   = (const int*)d_in[2];
    const int*   dst   = (const int*)d_in[3];
    const int*   gid   = (const int*)d_in[4];
    const float* W_emb = (const float*)d_in[5];
    const float* b_emb = (const float*)d_in[6];
    const float* gg_emb = (const float*)d_in[7];
    const float* be_emb = (const float*)d_in[8];
    const float* Wm  = (const float*)d_in[9];
    const float* bm  = (const float*)d_in[10];
    const float* gm  = (const float*)d_in[11];
    const float* bem = (const float*)d_in[12];
    const float* Ws  = (const float*)d_in[13];
    const float* bs  = (const float*)d_in[14];
    const float* gs  = (const float*)d_in[15];
    const float* bes = (const float*)d_in[16];
    const float* gn  = (const float*)d_in[17];
    const float* ben = (const float*)d_in[18];
    const float* Wf0 = (const float*)d_in[19];
    const float* bf0 = (const float*)d_in[20];
    const float* gf0 = (const float*)d_in[21];
    const float* bef0 = (const float*)d_in[22];
    const float* Wf1 = (const float*)d_in[23];
    const float* bf1 = (const float*)d_in[24];
    const float* gf1 = (const float*)d_in[25];
    const float* bef1 = (const float*)d_in[26];
    const float* Wt  = (const float*)d_in[27];
    const float* bt  = (const float*)d_in[28];
    float* out = (float*)d_out;

    float *pstats, *pstats2, *pbnpE, *pbnpN, *pr0, *pr1, *pr2;
    cudaGetSymbolAddress((void**)&pstats, g_stats);
    cudaGetSymbolAddress((void**)&pstats2, g_stats2);
    cudaGetSymbolAddress((void**)&pbnpE, g_bnpE);
    cudaGetSymbolAddress((void**)&pbnpN, g_bnpN);
    cudaGetSymbolAddress((void**)&pr0, g_r0);
    cudaGetSymbolAddress((void**)&pr1, g_r1);
    cudaGetSymbolAddress((void**)&pr2, g_r2);

    k_init<<<64, 256>>>();
    k_embed<<<512, 256>>>(nf, W_emb, b_emb);
    k_finalize<<<1, 64>>>(pstats2, pbnpN, 64, 1.f / NV);
    k_embed_apply<<<(NV * EE + 255) / 256, 256>>>(gg_emb, be_emb);

    for (int l = 0; l < NL; l++) {
        k_nodeproj<<<1024, 256>>>(Wm, Ws, l);
        k_cgemm<<<2048, 128>>>(ef, Wm, Ws, bm, bs, l);
        k_edgestats<<<2048, 256>>>(src, dst);
        k_finalize<<<1, 128>>>(pstats, pbnpE, 128, 1.f / ME);
        k_edgeapply<<<2048, 256>>>(src, dst, gm, bem, gs, bes, l);
        k_nodestats<<<1024, 256>>>();
        k_finalize<<<1, 64>>>(pstats2, pbnpN, 64, 1.f / NV);
        k_nodeapply<<<(NV * EE + 255) / 256, 256>>>(gn, ben, l);
    }

    k_pool<<<(NV + 255) / 256, 64>>>(gid);
    k_meanpool<<<(NG * EE + 255) / 256, 256>>>();
    k_fc<EE, FC0><<<FC0, NG>>>(pr0, Wf0, bf0, gf0, bef0, pr1);
    k_fc<FC0, FC1><<<FC1, NG>>>(pr1, Wf1, bf1, gf1, bef1, pr2);
    k_head<<<1, NG>>>(Wt, bt, out);
}

// round 3
// speedup vs baseline: 1.0929x; 1.0929x over previous
#include <cuda_runtime.h>
#include <cuda_fp16.h>
#include <math.h>

#define NV 50000
#define ME 800000
#define EE 64
#define FE 41
#define FV 92
#define NL 3
#define CC 169      // 2*EE + FE
#define FC0 128
#define FC1 64
#define NG 256
#define EPSB 1e-5f

// ---------------- scratch (device globals; no allocation allowed) ----------------
__device__ float g_tmp[NV * EE];                  // pre-BN embedding
__device__ float g_v[NV * EE];                    // node state
__device__ float g_A[4L * NV * EE];               // Am | Bm | As | Bs node projections
__device__ __half g_h[(size_t)ME * 128];          // per-edge pre-BN h, interleaved (hm[c],hs[c])
__device__ float g_agg[NV * EE];                  // scatter target
__device__ float g_stats[256];                    // edge stats: sum_m[64] sum_s[64] sq_m[64] sq_s[64]
__device__ float g_stats2[128];                   // node/embed stats: sum[64] sq[64]
__device__ float g_pool[NG * EE];
__device__ float g_cnt[NG];
__device__ float g_r0[NG * EE];
__device__ float g_r1[NG * FC0];
__device__ float g_r2[NG * FC1];

__device__ __forceinline__ float sigmoidf_(float x) { return 1.f / (1.f + __expf(-x)); }
__device__ __forceinline__ float softplusf_(float x) {
    return fmaxf(x, 0.f) + log1pf(__expf(-fabsf(x)));
}
__device__ __forceinline__ unsigned long long pack2_(float lo, float hi) {
    unsigned long long u;
    asm("mov.b64 %0,{%1,%2};" : "=l"(u) : "f"(lo), "f"(hi));
    return u;
}
__device__ __forceinline__ void ffma2_(unsigned long long& acc, unsigned long long a,
                                       unsigned long long b) {
    asm("fma.rn.f32x2 %0, %1, %2, %0;" : "+l"(acc) : "l"(a), "l"(b));
}
__device__ __forceinline__ float unpack_sum_(unsigned long long acc) {
    float lo, hi;
    asm("mov.b64 {%0,%1},%2;" : "=f"(lo), "=f"(hi) : "l"(acc));
    return lo + hi;
}

// ---------------- init: zero pool/cnt + embed stats ----------------
__global__ void k_init() {
    int i = blockIdx.x * blockDim.x + threadIdx.x;
    int stride = gridDim.x * blockDim.x;
    for (int j = i; j < NG * EE; j += stride) g_pool[j] = 0.f;
    for (int j = i; j < NG; j += stride) g_cnt[j] = 0.f;
    for (int j = i; j < 128; j += stride) g_stats2[j] = 0.f;
}

// ---------------- embedding GEMM + stats (f32x2 K-packed) ----------------
__global__ void k_embed(const float* __restrict__ nf, const float* __restrict__ W,
                        const float* __restrict__ b) {
    int tid = threadIdx.x;                 // 256
    int c = tid & 63, ry = tid >> 6;
    unsigned long long w2[FV / 2];         // 46 pairs
#pragma unroll
    for (int k2 = 0; k2 < FV / 2; k2++)
        w2[k2] = pack2_(W[(2 * k2) * EE + c], W[(2 * k2 + 1) * EE + c]);
    float bias = b[c];
    __shared__ __align__(16) float snf[4 * FV];
    __shared__ float sred[256];
    float s1 = 0.f, s2 = 0.f;
    for (int row0 = blockIdx.x * 4; row0 < NV; row0 += gridDim.x * 4) {
        __syncthreads();
        for (int i = tid; i < 4 * FV; i += 256) snf[i] = nf[(size_t)row0 * FV + i];
        __syncthreads();
        const unsigned long long* vp =
            reinterpret_cast<const unsigned long long*>(&snf[ry * FV]);
        unsigned long long acc = pack2_(bias, 0.f);
#pragma unroll
        for (int k2 = 0; k2 < FV / 2; k2++) ffma2_(acc, vp[k2], w2[k2]);
        float v = unpack_sum_(acc);
        g_tmp[(row0 + ry) * EE + c] = v;
        s1 += v; s2 += v * v;
    }
    __syncthreads();
    sred[tid] = s1; __syncthreads();
    if (tid < 64) atomicAdd(&g_stats2[tid], sred[tid] + sred[tid + 64] + sred[tid + 128] + sred[tid + 192]);
    __syncthreads();
    sred[tid] = s2; __syncthreads();
    if (tid < 64) atomicAdd(&g_stats2[64 + tid], sred[tid] + sred[tid + 64] + sred[tid + 128] + sred[tid + 192]);
}

// ---------------- embed BN + SiLU (inline finalize) ----------------
__global__ void k_embed_apply(const float* __restrict__ g, const float* __restrict__ be) {
    int i = blockIdx.x * blockDim.x + threadIdx.x;
    if (i >= NV * EE) return;
    int c = i & 63;
    float m = g_stats2[c] * (1.f / NV);
    float r = rsqrtf(g_stats2[64 + c] * (1.f / NV) - m * m + EPSB);
    float x = g_tmp[i];
    float xn = (x - m) * r * g[c] + be[c];
    g_v[i] = xn * sigmoidf_(xn);
}

// ---------------- node projections: A = v @ {Wm_src,Wm_dst,Ws_src,Ws_dst} ----------------
__global__ void k_nodeproj(const float* __restrict__ Wm, const float* __restrict__ Ws, int l) {
    if (blockIdx.x == 0 && threadIdx.x < 256) g_stats[threadIdx.x] = 0.f;  // zero edge stats
    int tid = threadIdx.x;
    int t = tid >> 6, col = tid & 63;
    const float* base = ((t < 2) ? Wm : Ws) + (size_t)l * CC * EE + (size_t)(t & 1) * (64 * EE) + col;
    unsigned long long w2[32];
#pragma unroll
    for (int k2 = 0; k2 < 32; k2++)
        w2[k2] = pack2_(base[(size_t)(2 * k2) * EE], base[(size_t)(2 * k2 + 1) * EE]);
    __shared__ __align__(16) float sv[256];
    float* outb = g_A + (size_t)t * NV * EE + col;
    for (int row0 = blockIdx.x * 4; row0 < NV; row0 += gridDim.x * 4) {
        __syncthreads();
        sv[tid] = g_v[row0 * EE + tid];
        __syncthreads();
#pragma unroll
        for (int r = 0; r < 4; r++) {
            const unsigned long long* vp =
                reinterpret_cast<const unsigned long long*>(&sv[r * 64]);
            unsigned long long acc = 0ULL;
#pragma unroll
            for (int k2 = 0; k2 < 32; k2++) ffma2_(acc, vp[k2], w2[k2]);
            outb[(size_t)(row0 + r) * EE] = unpack_sum_(acc);
        }
    }
}

// ---------------- fused edge pass 1: inline ef-GEMM + gathers + BN stats + h(fp16) ----------
__global__ void k_edgefused(const float* __restrict__ ef, const int* __restrict__ src,
                            const int* __restrict__ dst, const float* __restrict__ Wm,
                            const float* __restrict__ Ws, const float* __restrict__ bm,
                            const float* __restrict__ bs, int l) {
    int tid = threadIdx.x;   // 128
    // zero agg (consumed by pass 2)
    for (int i = blockIdx.x * 128 + tid; i < NV * EE; i += gridDim.x * 128) g_agg[i] = 0.f;
    int c = tid & 63;
    int half = tid >> 6;     // 0 gate, 1 screen
    const float* Wbase = (half ? Ws : Wm) + (size_t)l * CC * EE + (size_t)128 * EE + c;
    unsigned long long w2[22];
#pragma unroll
    for (int k2 = 0; k2 < 22; k2++) {
        float w0 = (2 * k2 < FE) ? Wbase[(size_t)(2 * k2) * EE] : 0.f;
        float w1 = (2 * k2 + 1 < FE) ? Wbase[(size_t)(2 * k2 + 1) * EE] : 0.f;
        w2[k2] = pack2_(w0, w1);
    }
    float bias = (half ? bs : bm)[l * EE + c];
    const float* A1 = g_A + (size_t)(2 * half) * NV * EE;       // src table
    const float* A2 = g_A + (size_t)(2 * half + 1) * NV * EE;   // dst table
    __shared__ __align__(16) float sef[4 * 44];
    __shared__ __align__(16) __half sh[4 * 128];
    float s1 = 0.f, s2 = 0.f;
    for (int e0 = blockIdx.x * 4; e0 < ME; e0 += gridDim.x * 4) {
        __syncthreads();
        for (int i = tid; i < 4 * FE; i += 128) {
            int r = i / FE, k = i - r * FE;
            sef[r * 44 + k] = ef[(size_t)e0 * FE + i];
        }
        if (tid < 12) { int r = tid / 3, k = FE + tid % 3; sef[r * 44 + k] = 0.f; }
        __syncthreads();
#pragma unroll
        for (int r = 0; r < 4; r++) {
            int e = e0 + r;
            int s = __ldg(src + e), d = __ldg(dst + e);
            float gsum = A1[s * EE + c] + A2[d * EE + c];
            const unsigned long long* ep =
                reinterpret_cast<const unsigned long long*>(&sef[r * 44]);
            unsigned long long acc = pack2_(bias, 0.f);
#pragma unroll
            for (int k2 = 0; k2 < 22; k2++) ffma2_(acc, ep[k2], w2[k2]);
            float h = unpack_sum_(acc) + gsum;
            s1 += h; s2 += h * h;
            sh[r * 128 + 2 * c + half] = __float2half_rn(h);
        }
        __syncthreads();
        const unsigned int* shp = reinterpret_cast<const unsigned int*>(sh);
        unsigned int* outp = reinterpret_cast<unsigned int*>(g_h) + (size_t)e0 * 64;
#pragma unroll
        for (int i = tid; i < 256; i += 128) outp[i] = shp[i];
    }
    atomicAdd(&g_stats[tid], s1);
    atomicAdd(&g_stats[128 + tid], s2);
}

// ---------------- edge pass 2: BN + sigmoid*softplus, scatter (float2 atomics) ----------
__global__ void k_edgeapply(const int* __restrict__ dst, const float* __restrict__ gm,
                            const float* __restrict__ bem, const float* __restrict__ gs,
                            const float* __restrict__ bes, int l) {
    int tid = threadIdx.x;   // 256
    if (blockIdx.x == 0 && tid < 128) g_stats2[tid] = 0.f;  // zero node stats
    int c2 = tid & 31, sub = tid >> 5;      // thread owns cols 2*c2, 2*c2+1; 8 edges per iter
    float invM = 1.f / ME;
    int c0 = 2 * c2, c1 = 2 * c2 + 1;
    float mm0 = g_stats[c0] * invM, mm1 = g_stats[c1] * invM;
    float ms0 = g_stats[64 + c0] * invM, ms1 = g_stats[64 + c1] * invM;
    float rm0 = rsqrtf(g_stats[128 + c0] * invM - mm0 * mm0 + EPSB);
    float rm1 = rsqrtf(g_stats[128 + c1] * invM - mm1 * mm1 + EPSB);
    float rs0 = rsqrtf(g_stats[192 + c0] * invM - ms0 * ms0 + EPSB);
    float rs1 = rsqrtf(g_stats[192 + c1] * invM - ms1 * ms1 + EPSB);
    float gmc0 = gm[l * EE + c0] * rm0, bemc0 = bem[l * EE + c0] - mm0 * gmc0;
    float gmc1 = gm[l * EE + c1] * rm1, bemc1 = bem[l * EE + c1] - mm1 * gmc1;
    float gsc0 = gs[l * EE + c0] * rs0, besc0 = bes[l * EE + c0] - ms0 * gsc0;
    float gsc1 = gs[l * EE + c1] * rs1, besc1 = bes[l * EE + c1] - ms1 * gsc1;
    const unsigned long long* hbuf = reinterpret_cast<const unsigned long long*>(g_h);
    for (int e = blockIdx.x * 8 + sub; e < ME; e += gridDim.x * 8) {
        int d = __ldg(dst + e);
        unsigned long long p = hbuf[(size_t)e * 32 + c2];
        __half2 h0 = *reinterpret_cast<__half2*>(&p);                       // (hm[c0], hs[c0])
        __half2 h1 = *(reinterpret_cast<__half2*>(&p) + 1);                 // (hm[c1], hs[c1])
        float hm0 = __low2float(h0), hs0 = __high2float(h0);
        float hm1 = __low2float(h1), hs1 = __high2float(h1);
        float o0 = sigmoidf_(fmaf(hm0, gmc0, bemc0)) * softplusf_(fmaf(hs0, gsc0, besc0));
        float o1 = sigmoidf_(fmaf(hm1, gmc1, bemc1)) * softplusf_(fmaf(hs1, gsc1, besc1));
        atomicAdd(reinterpret_cast<float2*>(&g_agg[d * EE + c0]), make_float2(o0, o1));
    }
}

// ---------------- node BN stats over N ----------------
__global__ void k_nodestats() {
    int tid = threadIdx.x;
    int c = tid & 63, sub = tid >> 6;
    float s1 = 0.f, s2 = 0.f;
    for (int n = blockIdx.x * 4 + sub; n < NV; n += gridDim.x * 4) {
        float x = g_agg[n * EE + c];
        s1 += x; s2 += x * x;
    }
    __shared__ float sred[256];
    sred[tid] = s1; __syncthreads();
    if (tid < 64) atomicAdd(&g_stats2[tid], sred[tid] + sred[tid + 64] + sred[tid + 128] + sred[tid + 192]);
    __syncthreads();
    sred[tid] = s2; __syncthreads();
    if (tid < 64) atomicAdd(&g_stats2[64 + tid], sred[tid] + sred[tid + 64] + sred[tid + 128] + sred[tid + 192]);
}

// ---------------- node update: v = softplus(BN(agg) + v), inline finalize ----------------
__global__ void k_nodeapply(const float* __restrict__ gn, const float* __restrict__ ben, int l) {
    int i = blockIdx.x * blockDim.x + threadIdx.x;
    if (i >= NV * EE) return;
    int c = i & 63;
    float m = g_stats2[c] * (1.f / NV);
    float r = rsqrtf(g_stats2[64 + c] * (1.f / NV) - m * m + EPSB);
    float a = g_agg[i];
    float an = (a - m) * r * gn[l * EE + c] + ben[l * EE + c];
    g_v[i] = softplusf_(an + g_v[i]);
}

// ---------------- graph pooling (graph_ids sorted -> run-length accumulate) ----------------
__global__ void k_pool(const int* __restrict__ gid) {
    __shared__ int sg[256];
    int tid = threadIdx.x;   // 64
    int n0 = blockIdx.x * 256;
    int nmax = min(256, NV - n0);
    for (int i = tid; i < nmax; i += 64) sg[i] = gid[n0 + i];
    __syncthreads();
    int cur = sg[0];
    float acc = 0.f, ccnt = 0.f;
    for (int i = 0; i < nmax; i++) {
        int g = sg[i];
        if (g != cur) {
            atomicAdd(&g_pool[cur * EE + tid], acc);
            if (tid == 0) atomicAdd(&g_cnt[cur], ccnt);
            acc = 0.f; ccnt = 0.f; cur = g;
        }
        acc += g_v[(n0 + i) * EE + tid];
        ccnt += 1.f;
    }
    atomicAdd(&g_pool[cur * EE + tid], acc);
    if (tid == 0) atomicAdd(&g_cnt[cur], ccnt);
}

__global__ void k_meanpool() {
    int i = blockIdx.x * blockDim.x + threadIdx.x;
    if (i < NG * EE) g_r0[i] = g_pool[i] / fmaxf(g_cnt[i >> 6], 1.f);
}

// ---------------- fused FC + BN(batch=256) + SiLU ----------------
template <int CI, int CO>
__global__ void k_fc(const float* __restrict__ in, const float* __restrict__ W,
                     const float* __restrict__ b, const float* __restrict__ gam,
                     const float* __restrict__ bet, float* __restrict__ out) {
    int r = threadIdx.x;   // 256 rows
    int co = blockIdx.x;
    float acc = b[co];
    for (int k = 0; k < CI; k++) acc = fmaf(in[r * CI + k], __ldg(&W[k * CO + co]), acc);
    __shared__ float sred[256];
    sred[r] = acc; __syncthreads();
    for (int s = 128; s > 0; s >>= 1) { if (r < s) sred[r] += sred[r + s]; __syncthreads(); }
    float m = sred[0] / 256.f;
    __syncthreads();
    sred[r] = acc * acc; __syncthreads();
    for (int s = 128; s > 0; s >>= 1) { if (r < s) sred[r] += sred[r + s]; __syncthreads(); }
    float var = sred[0] / 256.f - m * m;
    float rstd = rsqrtf(var + EPSB);
    float y = (acc - m) * rstd * gam[co] + bet[co];
    out[r * CO + co] = y * sigmoidf_(y);
}

__global__ void k_head(const float* __restrict__ Wt, const float* __restrict__ bt,
                       float* __restrict__ out) {
    int r = threadIdx.x;
    float acc = bt[0];
#pragma unroll
    for (int k = 0; k < FC1; k++) acc = fmaf(g_r2[r * FC1 + k], __ldg(&Wt[k]), acc);
    out[r] = acc;
}

// ---------------- launch ----------------
extern "C" void kernel_launch(void* const* d_in, const int* in_sizes, int n_in,
                              void* d_out, int out_size) {
    const float* nf    = (const float*)d_in[0];
    const float* ef    = (const float*)d_in[1];
    const int*   src   = (const int*)d_in[2];
    const int*   dst   = (const int*)d_in[3];
    const int*   gid   = (const int*)d_in[4];
    const float* W_emb = (const float*)d_in[5];
    const float* b_emb = (const float*)d_in[6];
    const float* gg_emb = (const float*)d_in[7];
    const float* be_emb = (const float*)d_in[8];
    const float* Wm  = (const float*)d_in[9];
    const float* bm  = (const float*)d_in[10];
    const float* gm  = (const float*)d_in[11];
    const float* bem = (const float*)d_in[12];
    const float* Ws  = (const float*)d_in[13];
    const float* bs  = (const float*)d_in[14];
    const float* gs  = (const float*)d_in[15];
    const float* bes = (const float*)d_in[16];
    const float* gn  = (const float*)d_in[17];
    const float* ben = (const float*)d_in[18];
    const float* Wf0 = (const float*)d_in[19];
    const float* bf0 = (const float*)d_in[20];
    const float* gf0 = (const float*)d_in[21];
    const float* bef0 = (const float*)d_in[22];
    const float* Wf1 = (const float*)d_in[23];
    const float* bf1 = (const float*)d_in[24];
    const float* gf1 = (const float*)d_in[25];
    const float* bef1 = (const float*)d_in[26];
    const float* Wt  = (const float*)d_in[27];
    const float* bt  = (const float*)d_in[28];
    float* out = (float*)d_out;

    float *pr0, *pr1, *pr2;
    cudaGetSymbolAddress((void**)&pr0, g_r0);
    cudaGetSymbolAddress((void**)&pr1, g_r1);
    cudaGetSymbolAddress((void**)&pr2, g_r2);

    k_init<<<64, 256>>>();
    k_embed<<<512, 256>>>(nf, W_emb, b_emb);
    k_embed_apply<<<(NV * EE + 255) / 256, 256>>>(gg_emb, be_emb);

    for (int l = 0; l < NL; l++) {
        k_nodeproj<<<1024, 256>>>(Wm, Ws, l);
        k_edgefused<<<2048, 128>>>(ef, src, dst, Wm, Ws, bm, bs, l);
        k_edgeapply<<<2048, 256>>>(dst, gm, bem, gs, bes, l);
        k_nodestats<<<1024, 256>>>();
        k_nodeapply<<<(NV * EE + 255) / 256, 256>>>(gn, ben, l);
    }

    k_pool<<<(NV + 255) / 256, 64>>>(gid);
    k_meanpool<<<(NG * EE + 255) / 256, 256>>>();
    k_fc<EE, FC0><<<FC0, NG>>>(pr0, Wf0, bf0, gf0, bef0, pr1);
    k_fc<FC0, FC1><<<FC1, NG>>>(pr1, Wf1, bf1, gf1, bef1, pr2);
    k_head<<<1, NG>>>(Wt, bt, out);
}